// round 5
// baseline (speedup 1.0000x reference)
#include <cuda_runtime.h>

#define B_   16
#define CIN  32
#define COUT 64
#define H_   16
#define W_   512
#define LRELU_SLOPE 0.3f
#define BN_EPS 1e-5f

typedef unsigned long long u64;

__device__ __forceinline__ void fma2(u64 &d, u64 a, u64 b) {
    asm("fma.rn.f32x2 %0,%1,%2,%0;" : "+l"(d) : "l"(a), "l"(b));
}
__device__ __forceinline__ void add2(u64 &d, u64 a) {
    asm("add.rn.f32x2 %0,%0,%1;" : "+l"(d) : "l"(a));
}
__device__ __forceinline__ void upk(u64 v, float &lo, float &hi) {
    asm("mov.b64 {%0,%1},%2;" : "=f"(lo), "=f"(hi) : "l"(v));
}
__device__ __forceinline__ u64 pk2(float lo, float hi) {
    u64 r; asm("mov.b64 %0,{%1,%2};" : "=l"(r) : "f"(lo), "f"(hi)); return r;
}

// ---- SMEM layout (float offsets) ----
#define SQ_OFF   0                   // Q  16x512
#define SK_OFF   8192                // K  16x512
#define SV_OFF   16384               // V  16x512
#define SPE_OFF  24576               // PE 16x512
#define SCR_OFF  32768               // 16640: conv staging 32x520 | sS 32x512 | epi tmpA+tmpB 2x8192
#define SQD_OFF  (SCR_OFF + 16640)   // 49408 : Qdup 16 x 64
#define SVN_OFF  (SQD_OFF + 1024)    // 50432 : VnPd 32 x 32 (dup'd V^T * rinv)
#define SWOFF    (SVN_OFF + 1024)    // 51456 : weights [4t][32ci][12] dup'd
#define SBIAS    (SWOFF + 1536)      // 52992 : 4 biases
#define SSUM     (SBIAS + 4)         // 52996 : 32 rows x 4 warp-partials
#define SMEM_FLOATS (SSUM + 128)     // 53124
#define SMEM_BYTES  (SMEM_FLOATS * 4)// 212496 B

#define XROW 520

__global__ __launch_bounds__(1024, 1)
void conv_attn_fused_kernel(
    const float* __restrict__ x,
    const float* __restrict__ wq, const float* __restrict__ gq, const float* __restrict__ bq, const float* __restrict__ mq, const float* __restrict__ vq,
    const float* __restrict__ wk, const float* __restrict__ gk, const float* __restrict__ bk, const float* __restrict__ mk, const float* __restrict__ vk,
    const float* __restrict__ wv, const float* __restrict__ gv, const float* __restrict__ bv, const float* __restrict__ mv, const float* __restrict__ vv,
    const float* __restrict__ wp, const float* __restrict__ gp, const float* __restrict__ bp, const float* __restrict__ mp, const float* __restrict__ vp,
    float* __restrict__ out)
{
    extern __shared__ float sm[];
    const int bid = blockIdx.x;
    const int b   = bid >> 6;
    const int c   = bid & 63;
    const int tid = threadIdx.x;

    // ---------------- BN-folded weights, duplicated taps ----------------
    if (tid < 160) {
        const int ci = tid / 5, kk = tid - ci * 5;
        const int src = c * 160 + ci * 5 + kk;
        const int dst = ci * 12 + 2 * kk;
        float s, a;
        s = gq[c] * rsqrtf(vq[c] + BN_EPS); a = wq[src] * s;
        sm[SWOFF + 0*384 + dst] = a; sm[SWOFF + 0*384 + dst + 1] = a;
        s = gk[c] * rsqrtf(vk[c] + BN_EPS); a = wk[src] * s;
        sm[SWOFF + 1*384 + dst] = a; sm[SWOFF + 1*384 + dst + 1] = a;
        s = gv[c] * rsqrtf(vv[c] + BN_EPS); a = wv[src] * s;
        sm[SWOFF + 2*384 + dst] = a; sm[SWOFF + 2*384 + dst + 1] = a;
        s = gp[c] * rsqrtf(vp[c] + BN_EPS); a = wp[src] * s;
        sm[SWOFF + 3*384 + dst] = a; sm[SWOFF + 3*384 + dst + 1] = a;
    }
    if (tid == 0) {
        float s;
        s = gq[c] * rsqrtf(vq[c] + BN_EPS); sm[SBIAS + 0] = bq[c] - mq[c] * s;
        s = gk[c] * rsqrtf(vk[c] + BN_EPS); sm[SBIAS + 1] = bk[c] - mk[c] * s;
        s = gv[c] * rsqrtf(vv[c] + BN_EPS); sm[SBIAS + 2] = bv[c] - mv[c] * s;
        s = gp[c] * rsqrtf(vp[c] + BN_EPS); sm[SBIAS + 3] = bp[c] - mp[c] * s;
    }
    if (tid < 128) {   // zero staging halos {2,3,516,517} per row
        int row = tid >> 2, q4 = tid & 3;
        int off = (q4 < 2) ? (2 + q4) : (514 + q4);
        sm[SCR_OFF + row * XROW + off] = 0.0f;
    }

    // ---------------- Conv(1x5)+BN+LeakyReLU : 1h x 4w per thread, 2 passes of 8h ----------
    const int hgrp = tid >> 7;           // 0..7
    const int w0   = (tid & 127) << 2;   // 4 w per thread
    const float* xb = x + (size_t)b * CIN * H_ * W_;

    for (int hb = 0; hb < 2; hb++) {
        u64 acc2[4][2];
        #pragma unroll
        for (int t = 0; t < 4; t++) { acc2[t][0] = 0ull; acc2[t][1] = 0ull; }

        for (int cib = 0; cib < 8; cib++) {
            // prefetch (4ci x 8h x 512) into regs before barrier
            float4 stg[4];
            #pragma unroll
            for (int it = 0; it < 4; it++) {
                int i  = tid + (it << 10);           // 0..4095 float4 index
                int ci = i >> 10, hh = (i >> 7) & 7, w4 = (i & 127) << 2;
                stg[it] = *(const float4*)&xb[(((size_t)(cib*4 + ci)) * H_ + (hb*8 + hh)) * W_ + w4];
            }
            __syncthreads();   // prior scratch consumers done
            #pragma unroll
            for (int it = 0; it < 4; it++) {
                int i  = tid + (it << 10);
                int ci = i >> 10, hh = (i >> 7) & 7, w4 = (i & 127) << 2;
                *(float4*)&sm[SCR_OFF + (ci*8 + hh) * XROW + 4 + w4] = stg[it];
            }
            __syncthreads();

            #pragma unroll
            for (int ci4 = 0; ci4 < 4; ci4++) {
                const float* xr = &sm[SCR_OFF + (ci4*8 + hgrp) * XROW + w0];
                float4 f0 = *(const float4*)(xr);        // staged w0-4..w0-1
                float4 f1 = *(const float4*)(xr + 4);    // w0..w0+3
                float4 f2 = *(const float4*)(xr + 8);    // w0+4..w0+7
                // P[n] = (x_{w0-2+n}, x_{w0-1+n}), n=0..6
                u64 P[7];
                P[0] = pk2(f0.z, f0.w); P[1] = pk2(f0.w, f1.x);
                P[2] = pk2(f1.x, f1.y); P[3] = pk2(f1.y, f1.z);
                P[4] = pk2(f1.z, f1.w); P[5] = pk2(f1.w, f2.x);
                P[6] = pk2(f2.x, f2.y);
                const int cig = cib*4 + ci4;
                #pragma unroll
                for (int t = 0; t < 4; t++) {
                    const float* wr = &sm[SWOFF + t*384 + cig*12];
                    ulonglong2 wa = *(const ulonglong2*)wr;
                    ulonglong2 wb2 = *(const ulonglong2*)(wr + 4);
                    u64 wc = *(const u64*)(wr + 8);
                    u64 w5[5] = { wa.x, wa.y, wb2.x, wb2.y, wc };
                    #pragma unroll
                    for (int k = 0; k < 5; k++) {
                        fma2(acc2[t][0], P[k],     w5[k]);   // outputs (w0, w0+1)
                        fma2(acc2[t][1], P[k + 2], w5[k]);   // outputs (w0+2, w0+3)
                    }
                }
            }
        }
        const int h = hb*8 + hgrp;
        float* dsts[4] = { sm + SQ_OFF, sm + SK_OFF, sm + SV_OFF, sm + SPE_OFF };
        #pragma unroll
        for (int t = 0; t < 4; t++) {
            float bias = sm[SBIAS + t];
            float y0, y1, y2, y3;
            upk(acc2[t][0], y0, y1); upk(acc2[t][1], y2, y3);
            y0 += bias; y1 += bias; y2 += bias; y3 += bias;
            y0 = (y0 >= 0.f) ? y0 : LRELU_SLOPE * y0;
            y1 = (y1 >= 0.f) ? y1 : LRELU_SLOPE * y1;
            y2 = (y2 >= 0.f) ? y2 : LRELU_SLOPE * y2;
            y3 = (y3 >= 0.f) ? y3 : LRELU_SLOPE * y3;
            *(float4*)&dsts[t][h * W_ + w0] = make_float4(y0, y1, y2, y3);
        }
    }
    __syncthreads();   // Q/K/V/PE ready

    // ---------------- Attention ----------------
    const int rgrpS = tid >> 7;          // 0..7 : S rows rgrpS*4..+3
    const int cb    = (tid & 127) << 2;  // 4 cols
    const int lane  = tid & 31, warp = tid >> 5;
    const int wslot = warp & 3;
    const int hh    = tid >> 9;          // 0/1 : h-half for out-update
    const int rgrpO = (tid >> 7) & 3;    // 0..3 : out r-range rgrpO*8..+8

    u64 oacc[8][2];                      // 8 h (this half) x 2 c-pairs
    #pragma unroll
    for (int i = 0; i < 8; i++) { oacc[i][0] = 0ull; oacc[i][1] = 0ull; }

    float* sS = sm + SCR_OFF;

    #pragma unroll 1
    for (int wb = 0; wb < W_; wb += 32) {
        // Qdup[h][2r{,+1}] = Q[h][wb+r] : 1024 floats, one per thread
        {
            int h2 = tid >> 6, idx = tid & 63;
            sm[SQD_OFF + tid] = sm[SQ_OFF + h2 * W_ + wb + (idx >> 1)];
        }
        __syncthreads();   // sync1: Qdup ready; prior-block sS/VnPd consumers done

        // --- S block: 4r x 4c (c-pair packed)
        u64 sacc[4][2];
        #pragma unroll
        for (int i = 0; i < 4; i++) { sacc[i][0] = 0ull; sacc[i][1] = 0ull; }

        #pragma unroll 8
        for (int h = 0; h < H_; h++) {
            ulonglong2 kk = *(const ulonglong2*)&sm[SK_OFF + h * W_ + cb];
            const ulonglong2* qd = (const ulonglong2*)&sm[SQD_OFF + h * 64 + rgrpS * 8];
            ulonglong2 q0 = qd[0];   // (dup r0, dup r1)
            ulonglong2 q1 = qd[1];   // (dup r2, dup r3)
            fma2(sacc[0][0], kk.x, q0.x); fma2(sacc[0][1], kk.y, q0.x);
            fma2(sacc[1][0], kk.x, q0.y); fma2(sacc[1][1], kk.y, q0.y);
            fma2(sacc[2][0], kk.x, q1.x); fma2(sacc[2][1], kk.y, q1.x);
            fma2(sacc[3][0], kk.x, q1.y); fma2(sacc[3][1], kk.y, q1.y);
        }

        // --- exp in regs (no max-sub: |S| small), store S, row partial sums
        float ps[4];
        #pragma unroll
        for (int i = 0; i < 4; i++) {
            float e0, e1, e2, e3;
            upk(sacc[i][0], e0, e1); upk(sacc[i][1], e2, e3);
            e0 = __expf(e0); e1 = __expf(e1); e2 = __expf(e2); e3 = __expf(e3);
            ps[i] = (e0 + e1) + (e2 + e3);
            *(float4*)&sS[(rgrpS*4 + i) * W_ + cb] = make_float4(e0, e1, e2, e3);
        }
        #pragma unroll
        for (int i = 0; i < 4; i++)
            #pragma unroll
            for (int o = 16; o; o >>= 1) ps[i] += __shfl_xor_sync(0xffffffffu, ps[i], o);
        if (lane == 0) {
            #pragma unroll
            for (int i = 0; i < 4; i++) sm[SSUM + (rgrpS*4 + i) * 4 + wslot] = ps[i];
        }
        __syncthreads();   // sync2: sums + exp'd S visible

        // --- VnPd[r][2h{,+1}] = V[h][wb+r] * rinv(r) : 1024 entries, one per thread
        {
            int r = tid >> 5, q = tid & 31, h2 = q >> 1;
            float4 p4 = *(const float4*)&sm[SSUM + r * 4];
            float rinv = __fdividef(1.0f, (p4.x + p4.y) + (p4.z + p4.w));
            sm[SVN_OFF + r * 32 + q] = sm[SV_OFF + h2 * W_ + wb + r] * rinv;
        }
        __syncthreads();   // sync3: VnPd ready

        // --- out-update: r = rgrpO*8..+8, h = hh*8..+7, c = cb..+3
        #pragma unroll
        for (int j = 0; j < 8; j++) {
            const int r = rgrpO*8 + j;
            const ulonglong2* ap = (const ulonglong2*)&sS[r * W_ + cb];
            ulonglong2 a2 = ap[0];                     // (pair c0c1, pair c2c3)
            const ulonglong2* vd = (const ulonglong2*)&sm[SVN_OFF + r * 32 + hh * 16];
            ulonglong2 v0 = vd[0], v1 = vd[1];         // 8 dup'd h values
            u64 vh[4] = { v0.x, v0.y, v1.x, v1.y };    // pairs (h0,h1),(h2,h3)... dup'd per h? 
            // NOTE: VnPd stores dup pairs: float idx q=2h{,+1} -> u64 n holds dup(h=n)
            fma2(oacc[0][0], a2.x, vh[0]); fma2(oacc[0][1], a2.y, vh[0]);
            fma2(oacc[1][0], a2.x, vh[1]); fma2(oacc[1][1], a2.y, vh[1]);
            fma2(oacc[2][0], a2.x, vh[2]); fma2(oacc[2][1], a2.y, vh[2]);
            fma2(oacc[3][0], a2.x, vh[3]); fma2(oacc[3][1], a2.y, vh[3]);
            ulonglong2 v2 = vd[2], v3 = vd[3];
            u64 vh2[4] = { v2.x, v2.y, v3.x, v3.y };
            fma2(oacc[4][0], a2.x, vh2[0]); fma2(oacc[4][1], a2.y, vh2[0]);
            fma2(oacc[5][0], a2.x, vh2[1]); fma2(oacc[5][1], a2.y, vh2[1]);
            fma2(oacc[6][0], a2.x, vh2[2]); fma2(oacc[6][1], a2.y, vh2[2]);
            fma2(oacc[7][0], a2.x, vh2[3]); fma2(oacc[7][1], a2.y, vh2[3]);
        }
        // next sync1 orders these reads before overwrite
    }
    __syncthreads();   // all out-updates done before scratch reuse

    // ---------------- Epilogue: combine 4 r-partials per h, add PE ----------------
    float* tmpA = sm + SCR_OFF;          // [16h][512c]
    float* tmpB = sm + SCR_OFF + 8192;
    if (rgrpO == 0) {
        #pragma unroll
        for (int i = 0; i < 8; i++)
            *(ulonglong2*)&tmpA[(hh*8 + i) * W_ + cb] = make_ulonglong2(oacc[i][0], oacc[i][1]);
    } else if (rgrpO == 1) {
        #pragma unroll
        for (int i = 0; i < 8; i++)
            *(ulonglong2*)&tmpB[(hh*8 + i) * W_ + cb] = make_ulonglong2(oacc[i][0], oacc[i][1]);
    }
    __syncthreads();
    if (rgrpO == 2) {
        #pragma unroll
        for (int i = 0; i < 8; i++) {
            u64* p = (u64*)&tmpA[(hh*8 + i) * W_ + cb];
            u64 a0 = p[0], a1 = p[1];
            add2(a0, oacc[i][0]); add2(a1, oacc[i][1]);
            p[0] = a0; p[1] = a1;
        }
    } else if (rgrpO == 3) {
        #pragma unroll
        for (int i = 0; i < 8; i++) {
            u64* p = (u64*)&tmpB[(hh*8 + i) * W_ + cb];
            u64 a0 = p[0], a1 = p[1];
            add2(a0, oacc[i][0]); add2(a1, oacc[i][1]);
            p[0] = a0; p[1] = a1;
        }
    }
    __syncthreads();

    float* og = out + (size_t)bid * (H_ * W_);
    #pragma unroll
    for (int it = 0; it < 2; it++) {
        int fi = (tid + (it << 10)) << 2;     // flat float index into 16x512
        int h  = fi >> 9, w = fi & 511;
        float4 ta = *(const float4*)&tmpA[h * W_ + w];
        float4 tb = *(const float4*)&tmpB[h * W_ + w];
        float4 pe = *(const float4*)&sm[SPE_OFF + h * W_ + w];
        *(float4*)&og[h * W_ + w] = make_float4(ta.x + tb.x + pe.x, ta.y + tb.y + pe.y,
                                                ta.z + tb.z + pe.z, ta.w + tb.w + pe.w);
    }
}

extern "C" void kernel_launch(void* const* d_in, const int* in_sizes, int n_in,
                              void* d_out, int out_size)
{
    cudaFuncSetAttribute(conv_attn_fused_kernel,
                         cudaFuncAttributeMaxDynamicSharedMemorySize, SMEM_BYTES);

    const float* x  = (const float*)d_in[0];
    const float* wq = (const float*)d_in[1];
    const float* gq = (const float*)d_in[2];
    const float* bq = (const float*)d_in[3];
    const float* mq = (const float*)d_in[4];
    const float* vq = (const float*)d_in[5];
    const float* wk = (const float*)d_in[6];
    const float* gk = (const float*)d_in[7];
    const float* bk = (const float*)d_in[8];
    const float* mk = (const float*)d_in[9];
    const float* vk = (const float*)d_in[10];
    const float* wv = (const float*)d_in[11];
    const float* gv = (const float*)d_in[12];
    const float* bv = (const float*)d_in[13];
    const float* mv = (const float*)d_in[14];
    const float* vv = (const float*)d_in[15];
    const float* wp = (const float*)d_in[16];
    const float* gp = (const float*)d_in[17];
    const float* bp = (const float*)d_in[18];
    const float* mp = (const float*)d_in[19];
    const float* vp = (const float*)d_in[20];

    conv_attn_fused_kernel<<<B_ * COUT, 1024, SMEM_BYTES>>>(
        x,
        wq, gq, bq, mq, vq,
        wk, gk, bk, mk, vk,
        wv, gv, bv, mv, vv,
        wp, gp, bp, mp, vp,
        (float*)d_out);
}

// round 6
// speedup vs baseline: 1.1081x; 1.1081x over previous
#include <cuda_runtime.h>

#define B_   16
#define CIN  32
#define COUT 64
#define H_   16
#define W_   512
#define LRELU_SLOPE 0.3f
#define BN_EPS 1e-5f

typedef unsigned long long u64;

__device__ __forceinline__ void fma2(u64 &d, u64 a, u64 b) {
    asm("fma.rn.f32x2 %0,%1,%2,%0;" : "+l"(d) : "l"(a), "l"(b));
}
__device__ __forceinline__ void add2(u64 &d, u64 a) {
    asm("add.rn.f32x2 %0,%0,%1;" : "+l"(d) : "l"(a));
}
__device__ __forceinline__ void upk(u64 v, float &lo, float &hi) {
    asm("mov.b64 {%0,%1},%2;" : "=f"(lo), "=f"(hi) : "l"(v));
}
__device__ __forceinline__ u64 pk2(float lo, float hi) {
    u64 r; asm("mov.b64 %0,{%1,%2};" : "=l"(r) : "f"(lo), "f"(hi)); return r;
}
__device__ __forceinline__ u64 dup2(float v) {
    u64 r; asm("mov.b64 %0,{%1,%1};" : "=l"(r) : "f"(v)); return r;
}

// ---- SMEM layout (float offsets) ----
#define SQ_OFF   0                   // Q  16x512
#define SK_OFF   8192                // K  16x512
#define SV_OFF   16384               // V  16x512
#define SPE_OFF  24576               // PE 16x512
#define SCR_OFF  32768               // 16640: conv staging 32x520 | sS 32x512 | epi tmp 16x512
#define SQD_OFF  (SCR_OFF + 16640)   // 49408 : Qdup 16 x 64 (dup'd Q slice)
#define SVN_OFF  (SQD_OFF + 1024)    // 50432 : VnP 32 x 20 natural (V^T * rinv, h-contig)
#define SWOFF    (SVN_OFF + 640)     // 51072 : weights [4t][32ci][12] dup'd
#define SBIAS    (SWOFF + 1536)      // 52608 : 4 biases
#define SSUM     (SBIAS + 4)         // 52612 : 32 rows x 4 warp-partials
#define SMEM_FLOATS (SSUM + 128)     // 52740
#define SMEM_BYTES  (SMEM_FLOATS * 4)// 210960 B

#define XROW 520

__global__ __launch_bounds__(512, 1)
void conv_attn_fused_kernel(
    const float* __restrict__ x,
    const float* __restrict__ wq, const float* __restrict__ gq, const float* __restrict__ bq, const float* __restrict__ mq, const float* __restrict__ vq,
    const float* __restrict__ wk, const float* __restrict__ gk, const float* __restrict__ bk, const float* __restrict__ mk, const float* __restrict__ vk,
    const float* __restrict__ wv, const float* __restrict__ gv, const float* __restrict__ bv, const float* __restrict__ mv, const float* __restrict__ vv,
    const float* __restrict__ wp, const float* __restrict__ gp, const float* __restrict__ bp, const float* __restrict__ mp, const float* __restrict__ vp,
    float* __restrict__ out)
{
    extern __shared__ float sm[];
    const int bid = blockIdx.x;
    const int b   = bid >> 6;
    const int c   = bid & 63;
    const int tid = threadIdx.x;

    // ---------------- BN-folded weights, duplicated taps ----------------
    if (tid < 160) {
        const int ci = tid / 5, kk = tid - ci * 5;
        const int src = c * 160 + ci * 5 + kk;
        const int dst = ci * 12 + 2 * kk;
        float s, a;
        s = gq[c] * rsqrtf(vq[c] + BN_EPS); a = wq[src] * s;
        sm[SWOFF + 0*384 + dst] = a; sm[SWOFF + 0*384 + dst + 1] = a;
        s = gk[c] * rsqrtf(vk[c] + BN_EPS); a = wk[src] * s;
        sm[SWOFF + 1*384 + dst] = a; sm[SWOFF + 1*384 + dst + 1] = a;
        s = gv[c] * rsqrtf(vv[c] + BN_EPS); a = wv[src] * s;
        sm[SWOFF + 2*384 + dst] = a; sm[SWOFF + 2*384 + dst + 1] = a;
        s = gp[c] * rsqrtf(vp[c] + BN_EPS); a = wp[src] * s;
        sm[SWOFF + 3*384 + dst] = a; sm[SWOFF + 3*384 + dst + 1] = a;
    }
    if (tid == 0) {
        float s;
        s = gq[c] * rsqrtf(vq[c] + BN_EPS); sm[SBIAS + 0] = bq[c] - mq[c] * s;
        s = gk[c] * rsqrtf(vk[c] + BN_EPS); sm[SBIAS + 1] = bk[c] - mk[c] * s;
        s = gv[c] * rsqrtf(vv[c] + BN_EPS); sm[SBIAS + 2] = bv[c] - mv[c] * s;
        s = gp[c] * rsqrtf(vp[c] + BN_EPS); sm[SBIAS + 3] = bp[c] - mp[c] * s;
    }
    if (tid < 128) {   // zero staging halos {2,3,516,517} per row
        int row = tid >> 2, q4 = tid & 3;
        int off = (q4 < 2) ? (2 + q4) : (514 + q4);
        sm[SCR_OFF + row * XROW + off] = 0.0f;
    }

    // ---------------- Conv(1x5)+BN+LeakyReLU : 8h x 8w thread tiles, 2 passes ----------------
    const int hgrp = tid >> 6;          // 0..7
    const int w0c  = (tid & 63) << 3;   // 0..504 step 8
    const float* xb = x + (size_t)b * CIN * H_ * W_;

    for (int hb = 0; hb < 2; hb++) {
        u64 acc2[4][4];
        #pragma unroll
        for (int t = 0; t < 4; t++)
            #pragma unroll
            for (int j = 0; j < 4; j++) acc2[t][j] = 0ull;

        for (int cib = 0; cib < 8; cib++) {
            float4 stg[8];
            #pragma unroll
            for (int it = 0; it < 8; it++) {
                int i  = tid + (it << 9);
                int ci = i >> 10, hh = (i >> 7) & 7, w4 = (i & 127) << 2;
                stg[it] = *(const float4*)&xb[(((size_t)(cib*4 + ci)) * H_ + (hb*8 + hh)) * W_ + w4];
            }
            __syncthreads();
            #pragma unroll
            for (int it = 0; it < 8; it++) {
                int i  = tid + (it << 9);
                int ci = i >> 10, hh = (i >> 7) & 7, w4 = (i & 127) << 2;
                *(float4*)&sm[SCR_OFF + (ci*8 + hh) * XROW + 4 + w4] = stg[it];
            }
            __syncthreads();

            #pragma unroll
            for (int ci4 = 0; ci4 < 4; ci4++) {
                const float* xr = &sm[SCR_OFF + (ci4*8 + hgrp) * XROW + w0c];
                float4 f0 = *(const float4*)(xr);
                float4 f1 = *(const float4*)(xr + 4);
                float4 f2 = *(const float4*)(xr + 8);
                float4 f3 = *(const float4*)(xr + 12);
                float xm[16] = {f0.x,f0.y,f0.z,f0.w, f1.x,f1.y,f1.z,f1.w,
                                f2.x,f2.y,f2.z,f2.w, f3.x,f3.y,f3.z,f3.w};
                u64 P[11];
                #pragma unroll
                for (int n = 0; n < 11; n++) P[n] = pk2(xm[n+2], xm[n+3]);
                const int cig = cib*4 + ci4;
                #pragma unroll
                for (int t = 0; t < 4; t++) {
                    const float* wr = &sm[SWOFF + t*384 + cig*12];
                    ulonglong2 wa = *(const ulonglong2*)wr;
                    ulonglong2 wb2 = *(const ulonglong2*)(wr + 4);
                    u64 wc = *(const u64*)(wr + 8);
                    u64 w5[5] = { wa.x, wa.y, wb2.x, wb2.y, wc };
                    #pragma unroll
                    for (int kk2 = 0; kk2 < 5; kk2++)
                        #pragma unroll
                        for (int jp = 0; jp < 4; jp++)
                            fma2(acc2[t][jp], P[2*jp + kk2], w5[kk2]);
                }
            }
        }
        const int h = hb*8 + hgrp;
        float* dsts[4] = { sm + SQ_OFF, sm + SK_OFF, sm + SV_OFF, sm + SPE_OFF };
        #pragma unroll
        for (int t = 0; t < 4; t++) {
            float bias = sm[SBIAS + t];
            float y[8];
            #pragma unroll
            for (int jp = 0; jp < 4; jp++) {
                float lo, hi; upk(acc2[t][jp], lo, hi);
                y[2*jp]   = lo + bias;
                y[2*jp+1] = hi + bias;
            }
            #pragma unroll
            for (int j = 0; j < 8; j++) y[j] = (y[j] >= 0.f) ? y[j] : LRELU_SLOPE * y[j];
            float* d = &dsts[t][h * W_ + w0c];
            *(float4*)(d)     = make_float4(y[0], y[1], y[2], y[3]);
            *(float4*)(d + 4) = make_float4(y[4], y[5], y[6], y[7]);
        }
    }
    __syncthreads();   // Q/K/V/PE ready

    // ---------------- Attention ----------------
    const int lane  = tid & 31, warp = tid >> 5;
    const int rgrpS = tid >> 7;          // 0..3 : S rows rgrpS*8..+7
    const int v4    = (tid & 127) << 2;  // S phase: 4 cols
    const int wslot = warp & 3;
    const int rgO   = tid >> 8;          // 0..1 : out r-range rgO*16..+15
    const int v2    = (tid & 255) << 1;  // out phase: 2 cols

    u64 oacc[8][2];                      // [hpair][vv] : (out[2hp][v2+vv], out[2hp+1][v2+vv])
    #pragma unroll
    for (int i = 0; i < 8; i++) { oacc[i][0] = 0ull; oacc[i][1] = 0ull; }

    float* sS = sm + SCR_OFF;            // 32 x 512 exp'd scores

    #pragma unroll 1
    for (int wb = 0; wb < W_; wb += 32) {
        // Qdup[h][2r{,+1}] = Q[h][wb+r] : one float2 per thread
        {
            int h2 = tid >> 5, r = lane;
            float qv = sm[SQ_OFF + h2 * W_ + wb + r];
            *(float2*)&sm[SQD_OFF + h2 * 64 + 2 * r] = make_float2(qv, qv);
        }
        __syncthreads();   // sync1: Qdup ready; prior-block sS/VnP reads done

        // --- S block: 8r x 4v (v-pair packed; K natural pairs, Q dup'd broadcast)
        u64 sacc[8][2];
        #pragma unroll
        for (int i = 0; i < 8; i++) { sacc[i][0] = 0ull; sacc[i][1] = 0ull; }

        #pragma unroll 8
        for (int h = 0; h < H_; h++) {
            ulonglong2 kk = *(const ulonglong2*)&sm[SK_OFF + h * W_ + v4];
            const ulonglong2* qd = (const ulonglong2*)&sm[SQD_OFF + h * 64 + rgrpS * 16];
            ulonglong2 qa = qd[0], qb = qd[1], qc = qd[2], qe = qd[3];  // 8 dup'd q (r0..r7)
            fma2(sacc[0][0], kk.x, qa.x); fma2(sacc[0][1], kk.y, qa.x);
            fma2(sacc[1][0], kk.x, qa.y); fma2(sacc[1][1], kk.y, qa.y);
            fma2(sacc[2][0], kk.x, qb.x); fma2(sacc[2][1], kk.y, qb.x);
            fma2(sacc[3][0], kk.x, qb.y); fma2(sacc[3][1], kk.y, qb.y);
            fma2(sacc[4][0], kk.x, qc.x); fma2(sacc[4][1], kk.y, qc.x);
            fma2(sacc[5][0], kk.x, qc.y); fma2(sacc[5][1], kk.y, qc.y);
            fma2(sacc[6][0], kk.x, qe.x); fma2(sacc[6][1], kk.y, qe.x);
            fma2(sacc[7][0], kk.x, qe.y); fma2(sacc[7][1], kk.y, qe.y);
        }

        // --- exp in regs (no max-sub: |S| small), store exp'd S, row partial sums
        float ps[8];
        #pragma unroll
        for (int i = 0; i < 8; i++) {
            float e0, e1, e2, e3;
            upk(sacc[i][0], e0, e1); upk(sacc[i][1], e2, e3);
            e0 = __expf(e0); e1 = __expf(e1); e2 = __expf(e2); e3 = __expf(e3);
            ps[i] = (e0 + e1) + (e2 + e3);
            *(float4*)&sS[(rgrpS*8 + i) * W_ + v4] = make_float4(e0, e1, e2, e3);
        }
        #pragma unroll
        for (int i = 0; i < 8; i++)
            #pragma unroll
            for (int o = 16; o; o >>= 1) ps[i] += __shfl_xor_sync(0xffffffffu, ps[i], o);
        if (lane == 0) {
            #pragma unroll
            for (int i = 0; i < 8; i++) sm[SSUM + (rgrpS*8 + i) * 4 + wslot] = ps[i];
        }
        __syncthreads();   // sync2: partial sums + exp'd S visible

        // --- VnP[r][h] = V[h][wb+r] * rinv(r), natural layout (stride 20)
        {
            int h2 = tid >> 5, r = lane;
            float4 p4 = *(const float4*)&sm[SSUM + r * 4];
            float rinv = __fdividef(1.0f, (p4.x + p4.y) + (p4.z + p4.w));
            sm[SVN_OFF + r * 20 + h2] = sm[SV_OFF + h2 * W_ + wb + r] * rinv;
        }
        __syncthreads();   // sync3: VnP ready

        // --- out-update: r = rgO*16..+15; h-pair packed; A read exactly once
        #pragma unroll 4
        for (int j = 0; j < 16; j++) {
            const int r = rgO*16 + j;
            float2 a2 = *(const float2*)&sS[r * W_ + v2];
            u64 d0 = dup2(a2.x), d1 = dup2(a2.y);
            const ulonglong2* vr = (const ulonglong2*)&sm[SVN_OFF + r * 20];
            ulonglong2 p0 = vr[0], p1 = vr[1];   // natural h-pairs: hp0..hp3
            fma2(oacc[0][0], p0.x, d0); fma2(oacc[0][1], p0.x, d1);
            fma2(oacc[1][0], p0.y, d0); fma2(oacc[1][1], p0.y, d1);
            fma2(oacc[2][0], p1.x, d0); fma2(oacc[2][1], p1.x, d1);
            fma2(oacc[3][0], p1.y, d0); fma2(oacc[3][1], p1.y, d1);
            ulonglong2 p2 = vr[2], p3 = vr[3];   // hp4..hp7
            fma2(oacc[4][0], p2.x, d0); fma2(oacc[4][1], p2.x, d1);
            fma2(oacc[5][0], p2.y, d0); fma2(oacc[5][1], p2.y, d1);
            fma2(oacc[6][0], p3.x, d0); fma2(oacc[6][1], p3.x, d1);
            fma2(oacc[7][0], p3.y, d0); fma2(oacc[7][1], p3.y, d1);
        }
        // next sync1 orders these reads before sS/VnP overwrite
    }
    __syncthreads();   // out-updates done before scratch reuse

    // ---------------- Epilogue: combine 2 r-split partials, add PE, store ----------------
    float* tmp = sm + SCR_OFF;           // [16h][512v] natural
    if (rgO == 0) {
        #pragma unroll
        for (int hp = 0; hp < 8; hp++) {
            float l0, h0, l1, h1;
            upk(oacc[hp][0], l0, h0); upk(oacc[hp][1], l1, h1);
            *(float2*)&tmp[(2*hp    ) * W_ + v2] = make_float2(l0, l1);
            *(float2*)&tmp[(2*hp + 1) * W_ + v2] = make_float2(h0, h1);
        }
    }
    __syncthreads();
    if (rgO == 1) {
        #pragma unroll
        for (int hp = 0; hp < 8; hp++) {
            float l0, h0, l1, h1;
            upk(oacc[hp][0], l0, h0); upk(oacc[hp][1], l1, h1);
            float2* p0 = (float2*)&tmp[(2*hp    ) * W_ + v2];
            float2* p1 = (float2*)&tmp[(2*hp + 1) * W_ + v2];
            float2 t0 = *p0, t1 = *p1;
            *p0 = make_float2(t0.x + l0, t0.y + l1);
            *p1 = make_float2(t1.x + h0, t1.y + h1);
        }
    }
    __syncthreads();

    float* og = out + (size_t)bid * (H_ * W_);
    #pragma unroll
    for (int it = 0; it < 4; it++) {
        int fi = (tid + (it << 9)) << 2;     // flat float index into 16x512
        int h  = fi >> 9, w = fi & 511;
        float4 tv = *(const float4*)&tmp[h * W_ + w];
        float4 pe = *(const float4*)&sm[SPE_OFF + h * W_ + w];
        *(float4*)&og[h * W_ + w] = make_float4(tv.x + pe.x, tv.y + pe.y,
                                                tv.z + pe.z, tv.w + pe.w);
    }
}

extern "C" void kernel_launch(void* const* d_in, const int* in_sizes, int n_in,
                              void* d_out, int out_size)
{
    cudaFuncSetAttribute(conv_attn_fused_kernel,
                         cudaFuncAttributeMaxDynamicSharedMemorySize, SMEM_BYTES);

    const float* x  = (const float*)d_in[0];
    const float* wq = (const float*)d_in[1];
    const float* gq = (const float*)d_in[2];
    const float* bq = (const float*)d_in[3];
    const float* mq = (const float*)d_in[4];
    const float* vq = (const float*)d_in[5];
    const float* wk = (const float*)d_in[6];
    const float* gk = (const float*)d_in[7];
    const float* bk = (const float*)d_in[8];
    const float* mk = (const float*)d_in[9];
    const float* vk = (const float*)d_in[10];
    const float* wv = (const float*)d_in[11];
    const float* gv = (const float*)d_in[12];
    const float* bv = (const float*)d_in[13];
    const float* mv = (const float*)d_in[14];
    const float* vv = (const float*)d_in[15];
    const float* wp = (const float*)d_in[16];
    const float* gp = (const float*)d_in[17];
    const float* bp = (const float*)d_in[18];
    const float* mp = (const float*)d_in[19];
    const float* vp = (const float*)d_in[20];

    conv_attn_fused_kernel<<<B_ * COUT, 512, SMEM_BYTES>>>(
        x,
        wq, gq, bq, mq, vq,
        wk, gk, bk, mk, vk,
        wv, gv, bv, mv, vv,
        wp, gp, bp, mp, vp,
        (float*)d_out);
}

// round 7
// speedup vs baseline: 1.1115x; 1.0031x over previous
#include <cuda_runtime.h>

#define B_   16
#define CIN  32
#define COUT 64
#define H_   16
#define W_   512
#define LRELU_SLOPE 0.3f
#define BN_EPS 1e-5f

typedef unsigned long long u64;

__device__ __forceinline__ void fma2(u64 &d, u64 a, u64 b) {
    asm("fma.rn.f32x2 %0,%1,%2,%0;" : "+l"(d) : "l"(a), "l"(b));
}
__device__ __forceinline__ void add2(u64 &d, u64 a) {
    asm("add.rn.f32x2 %0,%0,%1;" : "+l"(d) : "l"(a));
}
__device__ __forceinline__ void upk(u64 v, float &lo, float &hi) {
    asm("mov.b64 {%0,%1},%2;" : "=f"(lo), "=f"(hi) : "l"(v));
}
__device__ __forceinline__ u64 pk2(float lo, float hi) {
    u64 r; asm("mov.b64 %0,{%1,%2};" : "=l"(r) : "f"(lo), "f"(hi)); return r;
}
__device__ __forceinline__ u64 dup2(float v) {
    u64 r; asm("mov.b64 %0,{%1,%1};" : "=l"(r) : "f"(v)); return r;
}

// ---- SMEM layout (float offsets) ----
#define SQ_OFF   0                   // Q  16x512
#define SK_OFF   8192                // K  16x512
#define SV_OFF   16384               // V  16x512
#define SPE_OFF  24576               // PE 16x512
#define SCR_OFF  32768               // 16640: conv staging 32x520 | sS 32x512 | epi tmp 16x512
#define SQD_OFF  (SCR_OFF + 16640)   // 49408 : Qdup 16 x 64 (dup'd Q slice)
#define SVN_OFF  (SQD_OFF + 1024)    // 50432 : VnP 32 x 20 natural (V^T * rinv, h-contig)
#define SWOFF    (SVN_OFF + 640)     // 51072 : weights [4t][32ci][12] dup'd
#define SBIAS    (SWOFF + 1536)      // 52608 : 4 biases
#define SSUM     (SBIAS + 4)         // 52612 : 32 rows x 4 warp-partials
#define SMEM_FLOATS (SSUM + 128)     // 52740
#define SMEM_BYTES  (SMEM_FLOATS * 4)// 210960 B

#define XROW 520

__global__ __launch_bounds__(512, 1)
void conv_attn_fused_kernel(
    const float* __restrict__ x,
    const float* __restrict__ wq, const float* __restrict__ gq, const float* __restrict__ bq, const float* __restrict__ mq, const float* __restrict__ vq,
    const float* __restrict__ wk, const float* __restrict__ gk, const float* __restrict__ bk, const float* __restrict__ mk, const float* __restrict__ vk,
    const float* __restrict__ wv, const float* __restrict__ gv, const float* __restrict__ bv, const float* __restrict__ mv, const float* __restrict__ vv,
    const float* __restrict__ wp, const float* __restrict__ gp, const float* __restrict__ bp, const float* __restrict__ mp, const float* __restrict__ vp,
    float* __restrict__ out)
{
    extern __shared__ float sm[];
    const int bid = blockIdx.x;
    const int b   = bid >> 6;
    const int c   = bid & 63;
    const int tid = threadIdx.x;

    // ---------------- BN-folded weights, duplicated taps ----------------
    if (tid < 160) {
        const int ci = tid / 5, kk = tid - ci * 5;
        const int src = c * 160 + ci * 5 + kk;
        const int dst = ci * 12 + 2 * kk;
        float s, a;
        s = gq[c] * rsqrtf(vq[c] + BN_EPS); a = wq[src] * s;
        sm[SWOFF + 0*384 + dst] = a; sm[SWOFF + 0*384 + dst + 1] = a;
        s = gk[c] * rsqrtf(vk[c] + BN_EPS); a = wk[src] * s;
        sm[SWOFF + 1*384 + dst] = a; sm[SWOFF + 1*384 + dst + 1] = a;
        s = gv[c] * rsqrtf(vv[c] + BN_EPS); a = wv[src] * s;
        sm[SWOFF + 2*384 + dst] = a; sm[SWOFF + 2*384 + dst + 1] = a;
        s = gp[c] * rsqrtf(vp[c] + BN_EPS); a = wp[src] * s;
        sm[SWOFF + 3*384 + dst] = a; sm[SWOFF + 3*384 + dst + 1] = a;
    }
    if (tid == 0) {
        float s;
        s = gq[c] * rsqrtf(vq[c] + BN_EPS); sm[SBIAS + 0] = bq[c] - mq[c] * s;
        s = gk[c] * rsqrtf(vk[c] + BN_EPS); sm[SBIAS + 1] = bk[c] - mk[c] * s;
        s = gv[c] * rsqrtf(vv[c] + BN_EPS); sm[SBIAS + 2] = bv[c] - mv[c] * s;
        s = gp[c] * rsqrtf(vp[c] + BN_EPS); sm[SBIAS + 3] = bp[c] - mp[c] * s;
    }
    if (tid < 128) {   // zero staging halos {2,3,516,517} per row
        int row = tid >> 2, q4 = tid & 3;
        int off = (q4 < 2) ? (2 + q4) : (514 + q4);
        sm[SCR_OFF + row * XROW + off] = 0.0f;
    }

    // ---------------- Conv(1x5)+BN+LeakyReLU : 8h x 8w thread tiles, 2 passes ----------------
    const int hgrp = tid >> 6;          // 0..7
    const int w0c  = (tid & 63) << 3;   // 0..504 step 8
    const float* xb = x + (size_t)b * CIN * H_ * W_;

    for (int hb = 0; hb < 2; hb++) {
        u64 acc2[4][4];
        #pragma unroll
        for (int t = 0; t < 4; t++)
            #pragma unroll
            for (int j = 0; j < 4; j++) acc2[t][j] = 0ull;

        for (int cib = 0; cib < 8; cib++) {
            float4 stg[8];
            #pragma unroll
            for (int it = 0; it < 8; it++) {
                int i  = tid + (it << 9);
                int ci = i >> 10, hh = (i >> 7) & 7, w4 = (i & 127) << 2;
                stg[it] = *(const float4*)&xb[(((size_t)(cib*4 + ci)) * H_ + (hb*8 + hh)) * W_ + w4];
            }
            __syncthreads();
            #pragma unroll
            for (int it = 0; it < 8; it++) {
                int i  = tid + (it << 9);
                int ci = i >> 10, hh = (i >> 7) & 7, w4 = (i & 127) << 2;
                *(float4*)&sm[SCR_OFF + (ci*8 + hh) * XROW + 4 + w4] = stg[it];
            }
            __syncthreads();

            #pragma unroll
            for (int ci4 = 0; ci4 < 4; ci4++) {
                const float* xr = &sm[SCR_OFF + (ci4*8 + hgrp) * XROW + w0c];
                float4 f0 = *(const float4*)(xr);
                float4 f1 = *(const float4*)(xr + 4);
                float4 f2 = *(const float4*)(xr + 8);
                float4 f3 = *(const float4*)(xr + 12);
                float xm[16] = {f0.x,f0.y,f0.z,f0.w, f1.x,f1.y,f1.z,f1.w,
                                f2.x,f2.y,f2.z,f2.w, f3.x,f3.y,f3.z,f3.w};
                u64 P[11];
                #pragma unroll
                for (int n = 0; n < 11; n++) P[n] = pk2(xm[n+2], xm[n+3]);
                const int cig = cib*4 + ci4;
                #pragma unroll
                for (int t = 0; t < 4; t++) {
                    const float* wr = &sm[SWOFF + t*384 + cig*12];
                    ulonglong2 wa = *(const ulonglong2*)wr;
                    ulonglong2 wb2 = *(const ulonglong2*)(wr + 4);
                    u64 wc = *(const u64*)(wr + 8);
                    u64 w5[5] = { wa.x, wa.y, wb2.x, wb2.y, wc };
                    #pragma unroll
                    for (int kk2 = 0; kk2 < 5; kk2++)
                        #pragma unroll
                        for (int jp = 0; jp < 4; jp++)
                            fma2(acc2[t][jp], P[2*jp + kk2], w5[kk2]);
                }
            }
        }
        const int h = hb*8 + hgrp;
        float* dsts[4] = { sm + SQ_OFF, sm + SK_OFF, sm + SV_OFF, sm + SPE_OFF };
        #pragma unroll
        for (int t = 0; t < 4; t++) {
            float bias = sm[SBIAS + t];
            float y[8];
            #pragma unroll
            for (int jp = 0; jp < 4; jp++) {
                float lo, hi; upk(acc2[t][jp], lo, hi);
                y[2*jp]   = lo + bias;
                y[2*jp+1] = hi + bias;
            }
            #pragma unroll
            for (int j = 0; j < 8; j++) y[j] = (y[j] >= 0.f) ? y[j] : LRELU_SLOPE * y[j];
            float* d = &dsts[t][h * W_ + w0c];
            *(float4*)(d)     = make_float4(y[0], y[1], y[2], y[3]);
            *(float4*)(d + 4) = make_float4(y[4], y[5], y[6], y[7]);
        }
    }
    __syncthreads();   // Q/K/V/PE ready

    // ---------------- Attention ----------------
    const int lane  = tid & 31, warp = tid >> 5;
    const int rgrpS = tid >> 7;          // 0..3 : S rows rgrpS*8..+7
    const int v4    = (tid & 127) << 2;  // S phase: 4 cols
    const int wslot = warp & 3;
    const int rgO   = tid >> 8;          // 0..1 : out r-range rgO*16..+15
    const int v2    = (tid & 255) << 1;  // out phase: 2 cols

    u64 oacc[8][2];                      // [hpair][vv] : (out[2hp][v2+vv], out[2hp+1][v2+vv])
    #pragma unroll
    for (int i = 0; i < 8; i++) { oacc[i][0] = 0ull; oacc[i][1] = 0ull; }

    float* sS = sm + SCR_OFF;            // 32 x 512 exp'd scores

    #pragma unroll 1
    for (int wb = 0; wb < W_; wb += 32) {
        // Qdup[h][2r{,+1}] = Q[h][wb+r] : one float2 per thread
        {
            int h2 = tid >> 5, r = lane;
            float qv = sm[SQ_OFF + h2 * W_ + wb + r];
            *(float2*)&sm[SQD_OFF + h2 * 64 + 2 * r] = make_float2(qv, qv);
        }
        __syncthreads();   // sync1: Qdup ready; prior-block sS/VnP reads done

        // --- S block: 8r x 4v (v-pair packed; K natural pairs, Q dup'd broadcast)
        u64 sacc[8][2];
        #pragma unroll
        for (int i = 0; i < 8; i++) { sacc[i][0] = 0ull; sacc[i][1] = 0ull; }

        #pragma unroll 8
        for (int h = 0; h < H_; h++) {
            ulonglong2 kk = *(const ulonglong2*)&sm[SK_OFF + h * W_ + v4];
            const ulonglong2* qd = (const ulonglong2*)&sm[SQD_OFF + h * 64 + rgrpS * 16];
            ulonglong2 qa = qd[0], qb = qd[1], qc = qd[2], qe = qd[3];  // 8 dup'd q (r0..r7)
            fma2(sacc[0][0], kk.x, qa.x); fma2(sacc[0][1], kk.y, qa.x);
            fma2(sacc[1][0], kk.x, qa.y); fma2(sacc[1][1], kk.y, qa.y);
            fma2(sacc[2][0], kk.x, qb.x); fma2(sacc[2][1], kk.y, qb.x);
            fma2(sacc[3][0], kk.x, qb.y); fma2(sacc[3][1], kk.y, qb.y);
            fma2(sacc[4][0], kk.x, qc.x); fma2(sacc[4][1], kk.y, qc.x);
            fma2(sacc[5][0], kk.x, qc.y); fma2(sacc[5][1], kk.y, qc.y);
            fma2(sacc[6][0], kk.x, qe.x); fma2(sacc[6][1], kk.y, qe.x);
            fma2(sacc[7][0], kk.x, qe.y); fma2(sacc[7][1], kk.y, qe.y);
        }

        // --- exp in regs (no max-sub: |S| small), store exp'd S, row partial sums
        float ps[8];
        #pragma unroll
        for (int i = 0; i < 8; i++) {
            float e0, e1, e2, e3;
            upk(sacc[i][0], e0, e1); upk(sacc[i][1], e2, e3);
            e0 = __expf(e0); e1 = __expf(e1); e2 = __expf(e2); e3 = __expf(e3);
            ps[i] = (e0 + e1) + (e2 + e3);
            *(float4*)&sS[(rgrpS*8 + i) * W_ + v4] = make_float4(e0, e1, e2, e3);
        }
        #pragma unroll
        for (int i = 0; i < 8; i++)
            #pragma unroll
            for (int o = 16; o; o >>= 1) ps[i] += __shfl_xor_sync(0xffffffffu, ps[i], o);
        if (lane == 0) {
            #pragma unroll
            for (int i = 0; i < 8; i++) sm[SSUM + (rgrpS*8 + i) * 4 + wslot] = ps[i];
        }
        __syncthreads();   // sync2: partial sums + exp'd S visible

        // --- VnP[r][h] = V[h][wb+r] * rinv(r), natural layout (stride 20)
        {
            int h2 = tid >> 5, r = lane;
            float4 p4 = *(const float4*)&sm[SSUM + r * 4];
            float rinv = __fdividef(1.0f, (p4.x + p4.y) + (p4.z + p4.w));
            sm[SVN_OFF + r * 20 + h2] = sm[SV_OFF + h2 * W_ + wb + r] * rinv;
        }
        __syncthreads();   // sync3: VnP ready

        // --- out-update: r = rgO*16..+15; h-pair packed; A read exactly once
        #pragma unroll 4
        for (int j = 0; j < 16; j++) {
            const int r = rgO*16 + j;
            float2 a2 = *(const float2*)&sS[r * W_ + v2];
            u64 d0 = dup2(a2.x), d1 = dup2(a2.y);
            const ulonglong2* vr = (const ulonglong2*)&sm[SVN_OFF + r * 20];
            ulonglong2 p0 = vr[0], p1 = vr[1];   // natural h-pairs: hp0..hp3
            fma2(oacc[0][0], p0.x, d0); fma2(oacc[0][1], p0.x, d1);
            fma2(oacc[1][0], p0.y, d0); fma2(oacc[1][1], p0.y, d1);
            fma2(oacc[2][0], p1.x, d0); fma2(oacc[2][1], p1.x, d1);
            fma2(oacc[3][0], p1.y, d0); fma2(oacc[3][1], p1.y, d1);
            ulonglong2 p2 = vr[2], p3 = vr[3];   // hp4..hp7
            fma2(oacc[4][0], p2.x, d0); fma2(oacc[4][1], p2.x, d1);
            fma2(oacc[5][0], p2.y, d0); fma2(oacc[5][1], p2.y, d1);
            fma2(oacc[6][0], p3.x, d0); fma2(oacc[6][1], p3.x, d1);
            fma2(oacc[7][0], p3.y, d0); fma2(oacc[7][1], p3.y, d1);
        }
        // next sync1 orders these reads before sS/VnP overwrite
    }
    __syncthreads();   // out-updates done before scratch reuse

    // ---------------- Epilogue: combine 2 r-split partials, add PE, store ----------------
    float* tmp = sm + SCR_OFF;           // [16h][512v] natural
    if (rgO == 0) {
        #pragma unroll
        for (int hp = 0; hp < 8; hp++) {
            float l0, h0, l1, h1;
            upk(oacc[hp][0], l0, h0); upk(oacc[hp][1], l1, h1);
            *(float2*)&tmp[(2*hp    ) * W_ + v2] = make_float2(l0, l1);
            *(float2*)&tmp[(2*hp + 1) * W_ + v2] = make_float2(h0, h1);
        }
    }
    __syncthreads();
    if (rgO == 1) {
        #pragma unroll
        for (int hp = 0; hp < 8; hp++) {
            float l0, h0, l1, h1;
            upk(oacc[hp][0], l0, h0); upk(oacc[hp][1], l1, h1);
            float2* p0 = (float2*)&tmp[(2*hp    ) * W_ + v2];
            float2* p1 = (float2*)&tmp[(2*hp + 1) * W_ + v2];
            float2 t0 = *p0, t1 = *p1;
            *p0 = make_float2(t0.x + l0, t0.y + l1);
            *p1 = make_float2(t1.x + h0, t1.y + h1);
        }
    }
    __syncthreads();

    float* og = out + (size_t)bid * (H_ * W_);
    #pragma unroll
    for (int it = 0; it < 4; it++) {
        int fi = (tid + (it << 9)) << 2;     // flat float index into 16x512
        int h  = fi >> 9, w = fi & 511;
        float4 tv = *(const float4*)&tmp[h * W_ + w];
        float4 pe = *(const float4*)&sm[SPE_OFF + h * W_ + w];
        *(float4*)&og[h * W_ + w] = make_float4(tv.x + pe.x, tv.y + pe.y,
                                                tv.z + pe.z, tv.w + pe.w);
    }
}

extern "C" void kernel_launch(void* const* d_in, const int* in_sizes, int n_in,
                              void* d_out, int out_size)
{
    cudaFuncSetAttribute(conv_attn_fused_kernel,
                         cudaFuncAttributeMaxDynamicSharedMemorySize, SMEM_BYTES);

    const float* x  = (const float*)d_in[0];
    const float* wq = (const float*)d_in[1];
    const float* gq = (const float*)d_in[2];
    const float* bq = (const float*)d_in[3];
    const float* mq = (const float*)d_in[4];
    const float* vq = (const float*)d_in[5];
    const float* wk = (const float*)d_in[6];
    const float* gk = (const float*)d_in[7];
    const float* bk = (const float*)d_in[8];
    const float* mk = (const float*)d_in[9];
    const float* vk = (const float*)d_in[10];
    const float* wv = (const float*)d_in[11];
    const float* gv = (const float*)d_in[12];
    const float* bv = (const float*)d_in[13];
    const float* mv = (const float*)d_in[14];
    const float* vv = (const float*)d_in[15];
    const float* wp = (const float*)d_in[16];
    const float* gp = (const float*)d_in[17];
    const float* bp = (const float*)d_in[18];
    const float* mp = (const float*)d_in[19];
    const float* vp = (const float*)d_in[20];

    conv_attn_fused_kernel<<<B_ * COUT, 512, SMEM_BYTES>>>(
        x,
        wq, gq, bq, mq, vq,
        wk, gk, bk, mk, vk,
        wv, gv, bv, mv, vv,
        wp, gp, bp, mp, vp,
        (float*)d_out);
}

// round 8
// speedup vs baseline: 1.1736x; 1.0559x over previous
#include <cuda_runtime.h>

#define B_   16
#define CIN  32
#define COUT 64
#define H_   16
#define W_   512
#define LRELU_SLOPE 0.3f
#define BN_EPS 1e-5f

typedef unsigned long long u64;
typedef unsigned int u32;

__device__ __forceinline__ void fma2(u64 &d, u64 a, u64 b) {
    asm("fma.rn.f32x2 %0,%1,%2,%0;" : "+l"(d) : "l"(a), "l"(b));
}
__device__ __forceinline__ void upk(u64 v, float &lo, float &hi) {
    asm("mov.b64 {%0,%1},%2;" : "=f"(lo), "=f"(hi) : "l"(v));
}
__device__ __forceinline__ u64 pk2(float lo, float hi) {
    u64 r; asm("mov.b64 %0,{%1,%2};" : "=l"(r) : "f"(lo), "f"(hi)); return r;
}
__device__ __forceinline__ u64 dup2(float v) {
    u64 r; asm("mov.b64 %0,{%1,%1};" : "=l"(r) : "f"(v)); return r;
}
// pack (lo,hi) floats -> bf16x2 (lo in low 16 bits)
__device__ __forceinline__ u32 bfpair(float lo, float hi) {
    u32 r; asm("cvt.rn.satfinite.bf16x2.f32 %0, %1, %2;" : "=r"(r) : "f"(hi), "f"(lo)); return r;
}

// ---- SMEM layout (float offsets) ----
#define SQ_OFF   0                    // Q  16x512 fp32
#define SK_OFF   8192                 // K  16x512
#define SV_OFF   16384                // V  16x512
#define SPE_OFF  24576                // PE 16x512
#define SCR_OFF  32768                // 16640 fl: conv staging 32x520 | sS bf16 2x(32x512) (=16384 fl) | epi tmp 16x512
#define SVT_OFF  (SCR_OFF + 16640)    // 49408 : VT 2 x (32 x 20) unnormalized V^T
#define SSUMO    (SVT_OFF + 1280)     // 50688 : 2 x (32 rows x 4 warp-partials)
#define SWOFF    (SSUMO + 256)        // 50944 : weights [4t][32ci][12] dup'd
#define SBIAS    (SWOFF + 1536)       // 52480 : 4 biases
#define SMEM_FLOATS (SBIAS + 8)       // 52488
#define SMEM_BYTES  (SMEM_FLOATS * 4) // 209952 B

#define XROW 520

__global__ __launch_bounds__(512, 1)
void conv_attn_fused_kernel(
    const float* __restrict__ x,
    const float* __restrict__ wq, const float* __restrict__ gq, const float* __restrict__ bq, const float* __restrict__ mq, const float* __restrict__ vq,
    const float* __restrict__ wk, const float* __restrict__ gk, const float* __restrict__ bk, const float* __restrict__ mk, const float* __restrict__ vk,
    const float* __restrict__ wv, const float* __restrict__ gv, const float* __restrict__ bv, const float* __restrict__ mv, const float* __restrict__ vv,
    const float* __restrict__ wp, const float* __restrict__ gp, const float* __restrict__ bp, const float* __restrict__ mp, const float* __restrict__ vp,
    float* __restrict__ out)
{
    extern __shared__ float sm[];
    const int bid = blockIdx.x;
    const int b   = bid >> 6;
    const int c   = bid & 63;
    const int tid = threadIdx.x;

    // ---------------- BN-folded weights, duplicated taps ----------------
    if (tid < 160) {
        const int ci = tid / 5, kk = tid - ci * 5;
        const int src = c * 160 + ci * 5 + kk;
        const int dst = ci * 12 + 2 * kk;
        float s, a;
        s = gq[c] * rsqrtf(vq[c] + BN_EPS); a = wq[src] * s;
        sm[SWOFF + 0*384 + dst] = a; sm[SWOFF + 0*384 + dst + 1] = a;
        s = gk[c] * rsqrtf(vk[c] + BN_EPS); a = wk[src] * s;
        sm[SWOFF + 1*384 + dst] = a; sm[SWOFF + 1*384 + dst + 1] = a;
        s = gv[c] * rsqrtf(vv[c] + BN_EPS); a = wv[src] * s;
        sm[SWOFF + 2*384 + dst] = a; sm[SWOFF + 2*384 + dst + 1] = a;
        s = gp[c] * rsqrtf(vp[c] + BN_EPS); a = wp[src] * s;
        sm[SWOFF + 3*384 + dst] = a; sm[SWOFF + 3*384 + dst + 1] = a;
    }
    if (tid == 0) {
        float s;
        s = gq[c] * rsqrtf(vq[c] + BN_EPS); sm[SBIAS + 0] = bq[c] - mq[c] * s;
        s = gk[c] * rsqrtf(vk[c] + BN_EPS); sm[SBIAS + 1] = bk[c] - mk[c] * s;
        s = gv[c] * rsqrtf(vv[c] + BN_EPS); sm[SBIAS + 2] = bv[c] - mv[c] * s;
        s = gp[c] * rsqrtf(vp[c] + BN_EPS); sm[SBIAS + 3] = bp[c] - mp[c] * s;
    }
    if (tid < 128) {   // zero staging halos {2,3,516,517} per row
        int row = tid >> 2, q4 = tid & 3;
        int off = (q4 < 2) ? (2 + q4) : (514 + q4);
        sm[SCR_OFF + row * XROW + off] = 0.0f;
    }

    // ---------------- Conv(1x5)+BN+LeakyReLU : 8h x 8w thread tiles, 2 passes ----------------
    const int hgrp = tid >> 6;          // 0..7
    const int w0c  = (tid & 63) << 3;   // 0..504 step 8
    const float* xb = x + (size_t)b * CIN * H_ * W_;

    for (int hb = 0; hb < 2; hb++) {
        u64 acc2[4][4];
        #pragma unroll
        for (int t = 0; t < 4; t++)
            #pragma unroll
            for (int j = 0; j < 4; j++) acc2[t][j] = 0ull;

        for (int cib = 0; cib < 8; cib++) {
            float4 stg[8];
            #pragma unroll
            for (int it = 0; it < 8; it++) {
                int i  = tid + (it << 9);
                int ci = i >> 10, hh = (i >> 7) & 7, w4 = (i & 127) << 2;
                stg[it] = *(const float4*)&xb[(((size_t)(cib*4 + ci)) * H_ + (hb*8 + hh)) * W_ + w4];
            }
            __syncthreads();
            #pragma unroll
            for (int it = 0; it < 8; it++) {
                int i  = tid + (it << 9);
                int ci = i >> 10, hh = (i >> 7) & 7, w4 = (i & 127) << 2;
                *(float4*)&sm[SCR_OFF + (ci*8 + hh) * XROW + 4 + w4] = stg[it];
            }
            __syncthreads();

            #pragma unroll
            for (int ci4 = 0; ci4 < 4; ci4++) {
                const float* xr = &sm[SCR_OFF + (ci4*8 + hgrp) * XROW + w0c];
                float4 f0 = *(const float4*)(xr);
                float4 f1 = *(const float4*)(xr + 4);
                float4 f2 = *(const float4*)(xr + 8);
                float4 f3 = *(const float4*)(xr + 12);
                float xm[16] = {f0.x,f0.y,f0.z,f0.w, f1.x,f1.y,f1.z,f1.w,
                                f2.x,f2.y,f2.z,f2.w, f3.x,f3.y,f3.z,f3.w};
                u64 P[11];
                #pragma unroll
                for (int n = 0; n < 11; n++) P[n] = pk2(xm[n+2], xm[n+3]);
                const int cig = cib*4 + ci4;
                #pragma unroll
                for (int t = 0; t < 4; t++) {
                    const float* wr = &sm[SWOFF + t*384 + cig*12];
                    ulonglong2 wa = *(const ulonglong2*)wr;
                    ulonglong2 wb2 = *(const ulonglong2*)(wr + 4);
                    u64 wc = *(const u64*)(wr + 8);
                    u64 w5[5] = { wa.x, wa.y, wb2.x, wb2.y, wc };
                    #pragma unroll
                    for (int kk2 = 0; kk2 < 5; kk2++)
                        #pragma unroll
                        for (int jp = 0; jp < 4; jp++)
                            fma2(acc2[t][jp], P[2*jp + kk2], w5[kk2]);
                }
            }
        }
        const int h = hb*8 + hgrp;
        float* dsts[4] = { sm + SQ_OFF, sm + SK_OFF, sm + SV_OFF, sm + SPE_OFF };
        #pragma unroll
        for (int t = 0; t < 4; t++) {
            float bias = sm[SBIAS + t];
            float y[8];
            #pragma unroll
            for (int jp = 0; jp < 4; jp++) {
                float lo, hi; upk(acc2[t][jp], lo, hi);
                y[2*jp]   = lo + bias;
                y[2*jp+1] = hi + bias;
            }
            #pragma unroll
            for (int j = 0; j < 8; j++) y[j] = (y[j] >= 0.f) ? y[j] : LRELU_SLOPE * y[j];
            float* d = &dsts[t][h * W_ + w0c];
            *(float4*)(d)     = make_float4(y[0], y[1], y[2], y[3]);
            *(float4*)(d + 4) = make_float4(y[4], y[5], y[6], y[7]);
        }
    }
    __syncthreads();   // Q/K/V/PE ready

    // ---------------- Attention: fused produce(i)/consume(i-1), 1 sync per block -------------
    const int lane  = tid & 31, warp = tid >> 5;
    const int rgrpS = tid >> 7;          // 0..3 : S rows rgrpS*8..+7
    const int v4    = (tid & 127) << 2;  // S phase: 4 cols
    const int wslot = warp & 3;
    const int rgO   = tid >> 8;          // 0..1 : out r-range rgO*16..+15
    const int v2    = (tid & 255) << 1;  // out phase: 2 cols
    const int h2    = tid >> 5;          // 0..15 : VT build h

    u64 oacc[8][2];                      // [hpair][vv] : (out[2hp][v2+vv], out[2hp+1][v2+vv])
    #pragma unroll
    for (int i = 0; i < 8; i++) { oacc[i][0] = 0ull; oacc[i][1] = 0ull; }

    unsigned short* sb = (unsigned short*)(sm + SCR_OFF);   // 2 x 32x512 bf16 A-buffers

    #pragma unroll 1
    for (int i = 0; i <= 16; i++) {
        if (i < 16) {
            // ---- produce block i: S = Q^T K (rows wb..wb+31), exp, bf16 store, sums, VT ----
            const int wb = i << 5;
            const int pb = i & 1;
            u64 sacc[8][2];
            #pragma unroll
            for (int k = 0; k < 8; k++) { sacc[k][0] = 0ull; sacc[k][1] = 0ull; }

            #pragma unroll 8
            for (int h = 0; h < H_; h++) {
                ulonglong2 kk = *(const ulonglong2*)&sm[SK_OFF + h * W_ + v4];
                const float* qr = &sm[SQ_OFF + h * W_ + wb + (rgrpS << 3)];
                float4 qa = *(const float4*)qr;
                float4 qb = *(const float4*)(qr + 4);
                u64 d;
                d = dup2(qa.x); fma2(sacc[0][0], kk.x, d); fma2(sacc[0][1], kk.y, d);
                d = dup2(qa.y); fma2(sacc[1][0], kk.x, d); fma2(sacc[1][1], kk.y, d);
                d = dup2(qa.z); fma2(sacc[2][0], kk.x, d); fma2(sacc[2][1], kk.y, d);
                d = dup2(qa.w); fma2(sacc[3][0], kk.x, d); fma2(sacc[3][1], kk.y, d);
                d = dup2(qb.x); fma2(sacc[4][0], kk.x, d); fma2(sacc[4][1], kk.y, d);
                d = dup2(qb.y); fma2(sacc[5][0], kk.x, d); fma2(sacc[5][1], kk.y, d);
                d = dup2(qb.z); fma2(sacc[6][0], kk.x, d); fma2(sacc[6][1], kk.y, d);
                d = dup2(qb.w); fma2(sacc[7][0], kk.x, d); fma2(sacc[7][1], kk.y, d);
            }

            unsigned short* sbP = sb + pb * 16384;
            float ps[8];
            #pragma unroll
            for (int k = 0; k < 8; k++) {
                float e0, e1, e2, e3;
                upk(sacc[k][0], e0, e1); upk(sacc[k][1], e2, e3);
                e0 = __expf(e0); e1 = __expf(e1); e2 = __expf(e2); e3 = __expf(e3);
                ps[k] = (e0 + e1) + (e2 + e3);
                u32 lop = bfpair(e0, e1);
                u32 hip = bfpair(e2, e3);
                *(uint2*)&sbP[(rgrpS*8 + k) * W_ + v4] = make_uint2(lop, hip);
            }
            #pragma unroll
            for (int k = 0; k < 8; k++)
                #pragma unroll
                for (int o = 16; o; o >>= 1) ps[k] += __shfl_xor_sync(0xffffffffu, ps[k], o);
            if (lane == 0) {
                #pragma unroll
                for (int k = 0; k < 8; k++)
                    sm[SSUMO + pb*128 + (rgrpS*8 + k) * 4 + wslot] = ps[k];
            }
            // VT (unnormalized): VT[r][h2] = V[h2][wb+r]
            sm[SVT_OFF + pb*640 + lane * 20 + h2] = sm[SV_OFF + h2 * W_ + wb + lane];
        }

        if (i > 0) {
            // ---- consume block i-1: out += (V^T/rowsum) x A ----
            const int cbk = (i - 1) & 1;
            const unsigned short* sbC = sb + cbk * 16384;
            const float* vtC = sm + SVT_OFF + cbk * 640;
            const float* suC = sm + SSUMO + cbk * 128;
            #pragma unroll 4
            for (int j = 0; j < 16; j++) {
                const int r = rgO*16 + j;
                float4 p4 = *(const float4*)&suC[r * 4];
                float rinv = __fdividef(1.0f, (p4.x + p4.y) + (p4.z + p4.w));
                u32 ap = *(const u32*)&sbC[r * W_ + v2];
                float a0 = __uint_as_float(ap << 16) * rinv;
                float a1 = __uint_as_float(ap & 0xFFFF0000u) * rinv;
                u64 d0 = dup2(a0), d1 = dup2(a1);
                const ulonglong2* vr = (const ulonglong2*)&vtC[r * 20];
                ulonglong2 p0 = vr[0], p1 = vr[1];
                fma2(oacc[0][0], p0.x, d0); fma2(oacc[0][1], p0.x, d1);
                fma2(oacc[1][0], p0.y, d0); fma2(oacc[1][1], p0.y, d1);
                fma2(oacc[2][0], p1.x, d0); fma2(oacc[2][1], p1.x, d1);
                fma2(oacc[3][0], p1.y, d0); fma2(oacc[3][1], p1.y, d1);
                ulonglong2 p2 = vr[2], p3 = vr[3];
                fma2(oacc[4][0], p2.x, d0); fma2(oacc[4][1], p2.x, d1);
                fma2(oacc[5][0], p2.y, d0); fma2(oacc[5][1], p2.y, d1);
                fma2(oacc[6][0], p3.x, d0); fma2(oacc[6][1], p3.x, d1);
                fma2(oacc[7][0], p3.y, d0); fma2(oacc[7][1], p3.y, d1);
            }
        }
        __syncthreads();   // publish buf(i); next iter overwrites buf(i-1) safely
    }

    // ---------------- Epilogue: combine 2 r-split partials, add PE, store ----------------
    float* tmp = sm + SCR_OFF;           // [16h][512v] fp32 (reuses A-buffer space)
    if (rgO == 0) {
        #pragma unroll
        for (int hp = 0; hp < 8; hp++) {
            float l0, h0, l1, h1;
            upk(oacc[hp][0], l0, h0); upk(oacc[hp][1], l1, h1);
            *(float2*)&tmp[(2*hp    ) * W_ + v2] = make_float2(l0, l1);
            *(float2*)&tmp[(2*hp + 1) * W_ + v2] = make_float2(h0, h1);
        }
    }
    __syncthreads();
    if (rgO == 1) {
        #pragma unroll
        for (int hp = 0; hp < 8; hp++) {
            float l0, h0, l1, h1;
            upk(oacc[hp][0], l0, h0); upk(oacc[hp][1], l1, h1);
            float2* p0 = (float2*)&tmp[(2*hp    ) * W_ + v2];
            float2* p1 = (float2*)&tmp[(2*hp + 1) * W_ + v2];
            float2 t0 = *p0, t1 = *p1;
            *p0 = make_float2(t0.x + l0, t0.y + l1);
            *p1 = make_float2(t1.x + h0, t1.y + h1);
        }
    }
    __syncthreads();

    float* og = out + (size_t)bid * (H_ * W_);
    #pragma unroll
    for (int it = 0; it < 4; it++) {
        int fi = (tid + (it << 9)) << 2;     // flat float index into 16x512
        int h  = fi >> 9, w = fi & 511;
        float4 tv = *(const float4*)&tmp[h * W_ + w];
        float4 pe = *(const float4*)&sm[SPE_OFF + h * W_ + w];
        *(float4*)&og[h * W_ + w] = make_float4(tv.x + pe.x, tv.y + pe.y,
                                                tv.z + pe.z, tv.w + pe.w);
    }
}

extern "C" void kernel_launch(void* const* d_in, const int* in_sizes, int n_in,
                              void* d_out, int out_size)
{
    cudaFuncSetAttribute(conv_attn_fused_kernel,
                         cudaFuncAttributeMaxDynamicSharedMemorySize, SMEM_BYTES);

    const float* x  = (const float*)d_in[0];
    const float* wq = (const float*)d_in[1];
    const float* gq = (const float*)d_in[2];
    const float* bq = (const float*)d_in[3];
    const float* mq = (const float*)d_in[4];
    const float* vq = (const float*)d_in[5];
    const float* wk = (const float*)d_in[6];
    const float* gk = (const float*)d_in[7];
    const float* bk = (const float*)d_in[8];
    const float* mk = (const float*)d_in[9];
    const float* vk = (const float*)d_in[10];
    const float* wv = (const float*)d_in[11];
    const float* gv = (const float*)d_in[12];
    const float* bv = (const float*)d_in[13];
    const float* mv = (const float*)d_in[14];
    const float* vv = (const float*)d_in[15];
    const float* wp = (const float*)d_in[16];
    const float* gp = (const float*)d_in[17];
    const float* bp = (const float*)d_in[18];
    const float* mp = (const float*)d_in[19];
    const float* vp = (const float*)d_in[20];

    conv_attn_fused_kernel<<<B_ * COUT, 512, SMEM_BYTES>>>(
        x,
        wq, gq, bq, mq, vq,
        wk, gk, bk, mk, vk,
        wv, gv, bv, mv, vv,
        wp, gp, bp, mp, vp,
        (float*)d_out);
}

// round 10
// speedup vs baseline: 1.4071x; 1.1989x over previous
#include <cuda_runtime.h>
#include <cstdint>

#define B_   16
#define CIN  32
#define COUT 64
#define H_   16
#define W_   512
#define LRELU_SLOPE 0.3f
#define BN_EPS 1e-5f

typedef unsigned long long u64;
typedef unsigned int u32;

__device__ __forceinline__ void fma2(u64 &d, u64 a, u64 b) {
    asm("fma.rn.f32x2 %0,%1,%2,%0;" : "+l"(d) : "l"(a), "l"(b));
}
__device__ __forceinline__ void upk(u64 v, float &lo, float &hi) {
    asm("mov.b64 {%0,%1},%2;" : "=f"(lo), "=f"(hi) : "l"(v));
}
__device__ __forceinline__ u64 pk2(float lo, float hi) {
    u64 r; asm("mov.b64 %0,{%1,%2};" : "=l"(r) : "f"(lo), "f"(hi)); return r;
}
__device__ __forceinline__ u64 dup2(float v) {
    u64 r; asm("mov.b64 %0,{%1,%1};" : "=l"(r) : "f"(v)); return r;
}
// pack (lo,hi) floats -> bf16x2 (lo in low 16 bits)
__device__ __forceinline__ u32 bfpair(float lo, float hi) {
    u32 r; asm("cvt.rn.satfinite.bf16x2.f32 %0, %1, %2;" : "=r"(r) : "f"(hi), "f"(lo)); return r;
}
__device__ __forceinline__ u32 smem_u32_of(const void* p) {
    u32 a; asm("{ .reg .u64 t; cvta.to.shared.u64 t, %1; cvt.u32.u64 %0, t; }" : "=r"(a) : "l"(p));
    return a;
}

// ---- SMEM layout (float offsets) ----
#define SQ_OFF   0                    // Q  16x512 fp32
#define SK_OFF   8192                 // K  16x512
#define SV_OFF   16384                // V  16x512
#define SPE_OFF  24576                // PE 16x512
#define SCR_OFF  32768                // union: conv staging 32x520 (16640) | A bf16 2x(32 rows x 1024B swz)
#define SVN_OFF  49408                // Vn bf16 2 x (16 rows x 80B) = 640 fl ; byte 197632 (16B aligned)
#define SSUM     50048                // 2 x [32 w-rows][4 warp-partials]
#define SWOFF    50304                // weights [4t][32ci][12] dup'd
#define SBIAS    51840
#define SMEM_FLOATS 51848
#define SMEM_BYTES  (SMEM_FLOATS * 4) // 207392 B

#define SA_BYTE  131072               // = SCR_OFF*4
#define SVN_BYTE 197632               // = SVN_OFF*4

#define XROW 520

__global__ __launch_bounds__(512, 1)
void conv_attn_fused_kernel(
    const float* __restrict__ x,
    const float* __restrict__ wq, const float* __restrict__ gq, const float* __restrict__ bq, const float* __restrict__ mq, const float* __restrict__ vq,
    const float* __restrict__ wk, const float* __restrict__ gk, const float* __restrict__ bk, const float* __restrict__ mk, const float* __restrict__ vk,
    const float* __restrict__ wv, const float* __restrict__ gv, const float* __restrict__ bv, const float* __restrict__ mv, const float* __restrict__ vv,
    const float* __restrict__ wp, const float* __restrict__ gp, const float* __restrict__ bp, const float* __restrict__ mp, const float* __restrict__ vp,
    float* __restrict__ out)
{
    extern __shared__ float sm[];
    char* smb = (char*)sm;
    const int bid = blockIdx.x;
    const int b   = bid >> 6;
    const int c   = bid & 63;
    const int tid = threadIdx.x;
    const int warp = tid >> 5, lane = tid & 31;
    const u32 smem0 = smem_u32_of(sm);

    // ---------------- BN-folded weights, duplicated taps ----------------
    if (tid < 160) {
        const int ci = tid / 5, kk = tid - ci * 5;
        const int src = c * 160 + ci * 5 + kk;
        const int dst = ci * 12 + 2 * kk;
        float s, a;
        s = gq[c] * rsqrtf(vq[c] + BN_EPS); a = wq[src] * s;
        sm[SWOFF + 0*384 + dst] = a; sm[SWOFF + 0*384 + dst + 1] = a;
        s = gk[c] * rsqrtf(vk[c] + BN_EPS); a = wk[src] * s;
        sm[SWOFF + 1*384 + dst] = a; sm[SWOFF + 1*384 + dst + 1] = a;
        s = gv[c] * rsqrtf(vv[c] + BN_EPS); a = wv[src] * s;
        sm[SWOFF + 2*384 + dst] = a; sm[SWOFF + 2*384 + dst + 1] = a;
        s = gp[c] * rsqrtf(vp[c] + BN_EPS); a = wp[src] * s;
        sm[SWOFF + 3*384 + dst] = a; sm[SWOFF + 3*384 + dst + 1] = a;
    }
    if (tid == 0) {
        float s;
        s = gq[c] * rsqrtf(vq[c] + BN_EPS); sm[SBIAS + 0] = bq[c] - mq[c] * s;
        s = gk[c] * rsqrtf(vk[c] + BN_EPS); sm[SBIAS + 1] = bk[c] - mk[c] * s;
        s = gv[c] * rsqrtf(vv[c] + BN_EPS); sm[SBIAS + 2] = bv[c] - mv[c] * s;
        s = gp[c] * rsqrtf(vp[c] + BN_EPS); sm[SBIAS + 3] = bp[c] - mp[c] * s;
    }
    if (tid < 128) {   // zero staging halos {2,3,516,517} per row
        int row = tid >> 2, q4 = tid & 3;
        int off = (q4 < 2) ? (2 + q4) : (514 + q4);
        sm[SCR_OFF + row * XROW + off] = 0.0f;
    }

    // ---------------- Conv(1x5)+BN+LeakyReLU : 8h x 8w tiles, 2 passes (R8, verified) ------
    const int hgrp = tid >> 6;
    const int w0c  = (tid & 63) << 3;
    const float* xb = x + (size_t)b * CIN * H_ * W_;

    for (int hb = 0; hb < 2; hb++) {
        u64 acc2[4][4];
        #pragma unroll
        for (int t = 0; t < 4; t++)
            #pragma unroll
            for (int j = 0; j < 4; j++) acc2[t][j] = 0ull;

        for (int cib = 0; cib < 8; cib++) {
            float4 stg[8];
            #pragma unroll
            for (int it = 0; it < 8; it++) {
                int i  = tid + (it << 9);
                int ci = i >> 10, hh = (i >> 7) & 7, w4 = (i & 127) << 2;
                stg[it] = *(const float4*)&xb[(((size_t)(cib*4 + ci)) * H_ + (hb*8 + hh)) * W_ + w4];
            }
            __syncthreads();
            #pragma unroll
            for (int it = 0; it < 8; it++) {
                int i  = tid + (it << 9);
                int ci = i >> 10, hh = (i >> 7) & 7, w4 = (i & 127) << 2;
                *(float4*)&sm[SCR_OFF + (ci*8 + hh) * XROW + 4 + w4] = stg[it];
            }
            __syncthreads();

            #pragma unroll
            for (int ci4 = 0; ci4 < 4; ci4++) {
                const float* xr = &sm[SCR_OFF + (ci4*8 + hgrp) * XROW + w0c];
                float4 f0 = *(const float4*)(xr);
                float4 f1 = *(const float4*)(xr + 4);
                float4 f2 = *(const float4*)(xr + 8);
                float4 f3 = *(const float4*)(xr + 12);
                float xm[16] = {f0.x,f0.y,f0.z,f0.w, f1.x,f1.y,f1.z,f1.w,
                                f2.x,f2.y,f2.z,f2.w, f3.x,f3.y,f3.z,f3.w};
                u64 P[11];
                #pragma unroll
                for (int n = 0; n < 11; n++) P[n] = pk2(xm[n+2], xm[n+3]);
                const int cig = cib*4 + ci4;
                #pragma unroll
                for (int t = 0; t < 4; t++) {
                    const float* wr = &sm[SWOFF + t*384 + cig*12];
                    ulonglong2 wa = *(const ulonglong2*)wr;
                    ulonglong2 wb2 = *(const ulonglong2*)(wr + 4);
                    u64 wc = *(const u64*)(wr + 8);
                    u64 w5[5] = { wa.x, wa.y, wb2.x, wb2.y, wc };
                    #pragma unroll
                    for (int kk2 = 0; kk2 < 5; kk2++)
                        #pragma unroll
                        for (int jp = 0; jp < 4; jp++)
                            fma2(acc2[t][jp], P[2*jp + kk2], w5[kk2]);
                }
            }
        }
        const int h = hb*8 + hgrp;
        float* dsts[4] = { sm + SQ_OFF, sm + SK_OFF, sm + SV_OFF, sm + SPE_OFF };
        #pragma unroll
        for (int t = 0; t < 4; t++) {
            float bias = sm[SBIAS + t];
            float y[8];
            #pragma unroll
            for (int jp = 0; jp < 4; jp++) {
                float lo, hi; upk(acc2[t][jp], lo, hi);
                y[2*jp]   = lo + bias;
                y[2*jp+1] = hi + bias;
            }
            #pragma unroll
            for (int j = 0; j < 8; j++) y[j] = (y[j] >= 0.f) ? y[j] : LRELU_SLOPE * y[j];
            float* d = &dsts[t][h * W_ + w0c];
            *(float4*)(d)     = make_float4(y[0], y[1], y[2], y[3]);
            *(float4*)(d + 4) = make_float4(y[4], y[5], y[6], y[7]);
        }
    }
    __syncthreads();   // Q/K/V/PE ready; staging area becomes A-buffer

    // ---------------- Attention: S fp32 (FFMA2) -> A bf16 swz -> HMMA V x A ----------------
    const int rgrpS = tid >> 7;           // 0..3 : S rows rgrpS*8..+7 (w-rows)
    const int v4    = (tid & 127) << 2;   // 4 v-cols
    const int wslot = warp & 3;
    // ldmatrix lane mapping for A'[v][w] (x4.trans) : grp -> (voff, roff), alr = source row in 8
    const int agrp = lane >> 3, alr = lane & 7;
    const int a_voff = (agrp & 1) << 3;
    const int a_roff = (agrp >> 1) << 3;

    float acc[2][2][4];                   // [mi][ni][4] : D[v][h] fragments
    #pragma unroll
    for (int mi = 0; mi < 2; mi++)
        #pragma unroll
        for (int ni = 0; ni < 2; ni++)
            #pragma unroll
            for (int q = 0; q < 4; q++) acc[mi][ni][q] = 0.0f;

    #pragma unroll 1
    for (int i = 0; i <= 16; i++) {
        const int half = i & 1;
        if (i < 16) {
            // ---- produce block i: S[w][v] = sum_h Q[h][wb+w]*K[h][v]; exp; A bf16 swz; psums
            const int wb = i << 5;
            u64 sacc[8][2];
            #pragma unroll
            for (int k = 0; k < 8; k++) { sacc[k][0] = 0ull; sacc[k][1] = 0ull; }

            #pragma unroll 8
            for (int h = 0; h < H_; h++) {
                ulonglong2 kk = *(const ulonglong2*)&sm[SK_OFF + h * W_ + v4];
                const float* qr = &sm[SQ_OFF + h * W_ + wb + (rgrpS << 3)];
                float4 qa = *(const float4*)qr;
                float4 qb = *(const float4*)(qr + 4);
                u64 d;
                d = dup2(qa.x); fma2(sacc[0][0], kk.x, d); fma2(sacc[0][1], kk.y, d);
                d = dup2(qa.y); fma2(sacc[1][0], kk.x, d); fma2(sacc[1][1], kk.y, d);
                d = dup2(qa.z); fma2(sacc[2][0], kk.x, d); fma2(sacc[2][1], kk.y, d);
                d = dup2(qa.w); fma2(sacc[3][0], kk.x, d); fma2(sacc[3][1], kk.y, d);
                d = dup2(qb.x); fma2(sacc[4][0], kk.x, d); fma2(sacc[4][1], kk.y, d);
                d = dup2(qb.y); fma2(sacc[5][0], kk.x, d); fma2(sacc[5][1], kk.y, d);
                d = dup2(qb.z); fma2(sacc[6][0], kk.x, d); fma2(sacc[6][1], kk.y, d);
                d = dup2(qb.w); fma2(sacc[7][0], kk.x, d); fma2(sacc[7][1], kk.y, d);
            }

            char* aB = smb + SA_BYTE + half * 32768;
            float ps[8];
            #pragma unroll
            for (int k = 0; k < 8; k++) {
                float e0, e1, e2, e3;
                upk(sacc[k][0], e0, e1); upk(sacc[k][1], e2, e3);
                e0 = __expf(e0); e1 = __expf(e1); e2 = __expf(e2); e3 = __expf(e3);
                ps[k] = (e0 + e1) + (e2 + e3);
                u32 p0 = bfpair(e0, e1), p1 = bfpair(e2, e3);
                const int r = rgrpS * 8 + k;
                u32 bo = ((u32)(v4 * 2)) ^ ((u32)(k << 4));   // swizzle within 1024B row
                *(uint2*)(aB + r * 1024 + bo) = make_uint2(p0, p1);
            }
            #pragma unroll
            for (int k = 0; k < 8; k++)
                #pragma unroll
                for (int o = 16; o; o >>= 1) ps[k] += __shfl_xor_sync(0xffffffffu, ps[k], o);
            if (lane == 0) {
                #pragma unroll
                for (int k = 0; k < 8; k++)
                    sm[SSUM + half * 128 + (rgrpS * 8 + k) * 4 + wslot] = ps[k];
            }
        }
        __syncthreads();   // A(i) + psums(i) visible

        if (i < 16) {
            // ---- Vn[h][w] = V[h][wb+w] * rinv(w), bf16, 80B row stride (conflict-free ldmatrix)
            const int wb = i << 5;
            const int h2 = tid >> 5, r = lane;
            float4 p4 = *(const float4*)&sm[SSUM + half * 128 + r * 4];
            float rinv = __fdividef(1.0f, (p4.x + p4.y) + (p4.z + p4.w));
            float vn = sm[SV_OFF + h2 * W_ + wb + r] * rinv;
            *(unsigned short*)(smb + SVN_BYTE + half * 1280 + h2 * 80 + r * 2)
                = (unsigned short)(bfpair(vn, 0.0f) & 0xFFFFu);
        }

        if (i > 0) {
            // ---- consume block i-1 : D[v][h] += A'[v][w] * Vn[w][h]  (8 HMMA / warp)
            const int cbk = (i - 1) & 1;
            const u32 ab = smem0 + SA_BYTE + cbk * 32768;
            const u32 bb = smem0 + SVN_BYTE + cbk * 1280;
            u32 bfr[2][2][2];
            #pragma unroll
            for (int ni = 0; ni < 2; ni++)
                #pragma unroll
                for (int ks = 0; ks < 2; ks++) {
                    u32 addr = bb + (u32)((ni * 8 + (lane & 7)) * 80 + ks * 32 + ((lane >> 3) & 1) * 16);
                    asm volatile("ldmatrix.sync.aligned.m8n8.x2.shared.b16 {%0,%1}, [%2];"
                        : "=r"(bfr[ni][ks][0]), "=r"(bfr[ni][ks][1]) : "r"(addr));
                }
            #pragma unroll
            for (int mi = 0; mi < 2; mi++) {
                u32 af[2][4];
                #pragma unroll
                for (int ks = 0; ks < 2; ks++) {
                    const int r  = ks * 16 + a_roff + alr;
                    const int vb = (warp << 5) + (mi << 4) + a_voff;
                    u32 addr = ab + (u32)(r * 1024 + (((u32)(vb * 2)) ^ ((u32)(alr << 4))));
                    asm volatile("ldmatrix.sync.aligned.m8n8.x4.trans.shared.b16 {%0,%1,%2,%3}, [%4];"
                        : "=r"(af[ks][0]), "=r"(af[ks][1]), "=r"(af[ks][2]), "=r"(af[ks][3])
                        : "r"(addr));
                }
                #pragma unroll
                for (int ni = 0; ni < 2; ni++)
                    #pragma unroll
                    for (int ks = 0; ks < 2; ks++)
                        asm volatile(
                            "mma.sync.aligned.m16n8k16.row.col.f32.bf16.bf16.f32 "
                            "{%0,%1,%2,%3},{%4,%5,%6,%7},{%8,%9},{%0,%1,%2,%3};"
                            : "+f"(acc[mi][ni][0]), "+f"(acc[mi][ni][1]),
                              "+f"(acc[mi][ni][2]), "+f"(acc[mi][ni][3])
                            : "r"(af[ks][0]), "r"(af[ks][1]), "r"(af[ks][2]), "r"(af[ks][3]),
                              "r"(bfr[ni][ks][0]), "r"(bfr[ni][ks][1]));
            }
        }
        __syncthreads();   // Vn(i) published; A(i-1)/Vn(i-1) reads done before next overwrite
    }

    // ---------------- Epilogue: D + PE -> gmem straight from fragments ----------------
    float* og = out + (size_t)bid * (H_ * W_);
    {
        const int vb = (warp << 5) + (lane >> 2);
        const int hb2 = (lane & 3) << 1;
        #pragma unroll
        for (int mi = 0; mi < 2; mi++)
            #pragma unroll
            for (int ni = 0; ni < 2; ni++) {
                const int v = vb + (mi << 4);
                const int h = hb2 + (ni << 3);
                og[h * W_ + v]           = acc[mi][ni][0] + sm[SPE_OFF + h * W_ + v];
                og[(h + 1) * W_ + v]     = acc[mi][ni][1] + sm[SPE_OFF + (h + 1) * W_ + v];
                og[h * W_ + v + 8]       = acc[mi][ni][2] + sm[SPE_OFF + h * W_ + v + 8];
                og[(h + 1) * W_ + v + 8] = acc[mi][ni][3] + sm[SPE_OFF + (h + 1) * W_ + v + 8];
            }
    }
}

extern "C" void kernel_launch(void* const* d_in, const int* in_sizes, int n_in,
                              void* d_out, int out_size)
{
    cudaFuncSetAttribute(conv_attn_fused_kernel,
                         cudaFuncAttributeMaxDynamicSharedMemorySize, SMEM_BYTES);

    const float* x  = (const float*)d_in[0];
    const float* wq = (const float*)d_in[1];
    const float* gq = (const float*)d_in[2];
    const float* bq = (const float*)d_in[3];
    const float* mq = (const float*)d_in[4];
    const float* vq = (const float*)d_in[5];
    const float* wk = (const float*)d_in[6];
    const float* gk = (const float*)d_in[7];
    const float* bk = (const float*)d_in[8];
    const float* mk = (const float*)d_in[9];
    const float* vk = (const float*)d_in[10];
    const float* wv = (const float*)d_in[11];
    const float* gv = (const float*)d_in[12];
    const float* bv = (const float*)d_in[13];
    const float* mv = (const float*)d_in[14];
    const float* vv = (const float*)d_in[15];
    const float* wp = (const float*)d_in[16];
    const float* gp = (const float*)d_in[17];
    const float* bp = (const float*)d_in[18];
    const float* mp = (const float*)d_in[19];
    const float* vp = (const float*)d_in[20];

    conv_attn_fused_kernel<<<B_ * COUT, 512, SMEM_BYTES>>>(
        x,
        wq, gq, bq, mq, vq,
        wk, gk, bk, mk, vk,
        wv, gv, bv, mv, vv,
        wp, gp, bp, mp, vp,
        (float*)d_out);
}